// round 2
// baseline (speedup 1.0000x reference)
#include <cuda_runtime.h>

#define HS 16

// ---- fast near-exact activations (ex2 err ~2^-22, rcp err ~2^-23) ----
__device__ __forceinline__ float ex2a(float x) { float r; asm("ex2.approx.f32 %0, %1;" : "=f"(r) : "f"(x)); return r; }
__device__ __forceinline__ float rcpa(float x) { float r; asm("rcp.approx.f32 %0, %1;" : "=f"(r) : "f"(x)); return r; }
// sigmoid(x) = 1/(1+2^(-x*log2e))
__device__ __forceinline__ float sigf(float x) { return rcpa(1.0f + ex2a(x * -1.4426950408889634f)); }
// tanh(x) = 2/(1+2^(-2x*log2e)) - 1
__device__ __forceinline__ float tnhf(float x) { return fmaf(2.0f, rcpa(1.0f + ex2a(x * -2.8853900817779268f)), -1.0f); }

__global__ void __launch_bounds__(256, 2) infect_lstm_kernel(
    const float* __restrict__ mob,   // [B,7]
    const float* __restrict__ ctrl,  // [B,5]
    const float* __restrict__ Wcc,   // [3,5]
    const float* __restrict__ bcc,   // [3]
    const float* __restrict__ Wih,   // [64,1]  gate-major i,f,g,o
    const float* __restrict__ Whh,   // [64,16]
    const float* __restrict__ bih,   // [64]
    const float* __restrict__ bhh,   // [64]
    const float* __restrict__ W1,    // [16,19]
    const float* __restrict__ b1,    // [16]
    const float* __restrict__ W2,    // [16,16]
    const float* __restrict__ b2,    // [16]
    const float* __restrict__ W3,    // [1,16]
    const float* __restrict__ b3,    // [1]
    float* __restrict__ out)         // [B]
{
    // Weights in shared memory; all accesses are warp-uniform -> broadcast, no conflicts.
    __shared__ __align__(16) float4 sWhh[HS * HS];   // [k][m] -> (i,f,g,o)
    __shared__ __align__(16) float4 sWih[HS];        // [k]    -> (i,f,g,o)
    __shared__ __align__(16) float4 sBias[HS];       // [k]    -> b_ih+b_hh per gate
    __shared__ float sW1[16 * 19];
    __shared__ float sB1[16];
    __shared__ float sW2[16 * 16];
    __shared__ float sB2[16];
    __shared__ float sW3[16];
    __shared__ float sWcc[3 * 5];
    __shared__ float sBcc[3];
    __shared__ float sB3;

    const int tid = threadIdx.x;

    for (int i = tid; i < HS * HS; i += 256) {
        int m = i & 15, k = i >> 4;
        sWhh[i] = make_float4(Whh[(0 * 16 + k) * 16 + m],
                              Whh[(1 * 16 + k) * 16 + m],
                              Whh[(2 * 16 + k) * 16 + m],
                              Whh[(3 * 16 + k) * 16 + m]);
    }
    if (tid < HS) {
        int k = tid;
        sWih[k]  = make_float4(Wih[0 * 16 + k], Wih[1 * 16 + k], Wih[2 * 16 + k], Wih[3 * 16 + k]);
        sBias[k] = make_float4(bih[0 * 16 + k] + bhh[0 * 16 + k],
                               bih[1 * 16 + k] + bhh[1 * 16 + k],
                               bih[2 * 16 + k] + bhh[2 * 16 + k],
                               bih[3 * 16 + k] + bhh[3 * 16 + k]);
    }
    for (int i = tid; i < 16 * 19; i += 256) sW1[i] = W1[i];
    for (int i = tid; i < 16 * 16; i += 256) sW2[i] = W2[i];
    if (tid < 16) sB1[tid] = b1[tid];
    else if (tid < 32) sB2[tid - 16] = b2[tid - 16];
    else if (tid < 48) sW3[tid - 32] = W3[tid - 32];
    else if (tid < 63) sWcc[tid - 48] = Wcc[tid - 48];
    else if (tid < 66) sBcc[tid - 63] = bcc[tid - 63];
    else if (tid == 66) sB3 = b3[0];
    __syncthreads();

    const int t = blockIdx.x * 256 + tid;
    const float* mp = mob + (size_t)t * 7;
    const float* cp = ctrl + (size_t)t * 5;

    // preload per-element inputs
    float xm[7];
#pragma unroll
    for (int s = 0; s < 7; s++) xm[s] = mp[s];
    float cin[5];
#pragma unroll
    for (int i = 0; i < 5; i++) cin[i] = cp[i];

    // ---- control head: Linear(5->3) ----
    float ctl[3];
#pragma unroll
    for (int j = 0; j < 3; j++) {
        float acc = sBcc[j];
#pragma unroll
        for (int i = 0; i < 5; i++) acc = fmaf(cin[i], sWcc[j * 5 + i], acc);
        ctl[j] = acc;
    }

    // ---- LSTM: 7 steps, H=16 ----
    float h[HS], c[HS];
#pragma unroll
    for (int k = 0; k < HS; k++) { h[k] = 0.0f; c[k] = 0.0f; }

#pragma unroll 1
    for (int s = 0; s < 7; s++) {
        const float x = xm[s];
        float hn[HS];
#pragma unroll
        for (int k = 0; k < HS; k++) {
            float4 wx = sWih[k];
            float4 bb = sBias[k];
            float ai = fmaf(x, wx.x, bb.x);
            float af = fmaf(x, wx.y, bb.y);
            float ag = fmaf(x, wx.z, bb.z);
            float ao = fmaf(x, wx.w, bb.w);
#pragma unroll
            for (int m = 0; m < HS; m++) {
                float4 w = sWhh[k * HS + m];
                float hm = h[m];
                ai = fmaf(hm, w.x, ai);
                af = fmaf(hm, w.y, af);
                ag = fmaf(hm, w.z, ag);
                ao = fmaf(hm, w.w, ao);
            }
            float ig = sigf(ai);
            float fg = sigf(af);
            float gg = tnhf(ag);
            float og = sigf(ao);
            float ck = fmaf(fg, c[k], ig * gg);
            c[k] = ck;
            hn[k] = og * tnhf(ck);
        }
#pragma unroll
        for (int k = 0; k < HS; k++) h[k] = hn[k];
    }

    // ---- FC head: (19->16) tanh, (16->16) tanh, (16->1) relu ----
    float x1[16];
#pragma unroll
    for (int j = 0; j < 16; j++) {
        float acc = sB1[j];
#pragma unroll
        for (int i = 0; i < 16; i++) acc = fmaf(h[i], sW1[j * 19 + i], acc);
#pragma unroll
        for (int i = 0; i < 3; i++)  acc = fmaf(ctl[i], sW1[j * 19 + 16 + i], acc);
        x1[j] = tnhf(acc);
    }
    float x2[16];
#pragma unroll
    for (int j = 0; j < 16; j++) {
        float acc = sB2[j];
#pragma unroll
        for (int i = 0; i < 16; i++) acc = fmaf(x1[i], sW2[j * 16 + i], acc);
        x2[j] = tnhf(acc);
    }
    float acc = sB3;
#pragma unroll
    for (int i = 0; i < 16; i++) acc = fmaf(x2[i], sW3[i], acc);

    out[t] = fmaxf(acc, 0.0f);
}

extern "C" void kernel_launch(void* const* d_in, const int* in_sizes, int n_in,
                              void* d_out, int out_size)
{
    const float* mob  = (const float*)d_in[0];
    const float* ctrl = (const float*)d_in[1];
    // d_in[2] = "last" -- unused by the model (its size gives B)
    const float* Wcc  = (const float*)d_in[3];
    const float* bcc  = (const float*)d_in[4];
    const float* Wih  = (const float*)d_in[5];
    const float* Whh  = (const float*)d_in[6];
    const float* bih  = (const float*)d_in[7];
    const float* bhh  = (const float*)d_in[8];
    const float* W1   = (const float*)d_in[9];
    const float* b1   = (const float*)d_in[10];
    const float* W2   = (const float*)d_in[11];
    const float* b2   = (const float*)d_in[12];
    const float* W3   = (const float*)d_in[13];
    const float* b3   = (const float*)d_in[14];

    int B = in_sizes[2];
    int blocks = (B + 255) / 256;

    infect_lstm_kernel<<<blocks, 256>>>(mob, ctrl, Wcc, bcc, Wih, Whh, bih, bhh,
                                        W1, b1, W2, b2, W3, b3, (float*)d_out);
}